// round 17
// baseline (speedup 1.0000x reference)
#include <cuda_runtime.h>

// CGCoupler: out[n, ro[m]] += x1[n, r1[m]] * x2[n, r2[m]] * cg[m]
//
// prep (1 CTA, 1024 thr, rank-based, no serial chains) -- unchanged from R16:
//   run starts partition [0,M) (deg = next_start - start); coalesced flag +
//   unordered append; order by parallel rank; bin by ro_0; rank-based canonical
//   placement (deg desc, r1, r2); per-column {start|ns<<16, eff}.
// couple (NEW: 8-row subtiles, 1 col/thread, TPB=640, 2 CTAs/SM):
//   x subtiles staged as TWO 4-row-interleaved float4 blocks (rows 0-3 at [i],
//   rows 4-7 at [rep_dim+i]) -> per entry: 1 broadcast pts + 4 lane-consecutive
//   LDS.128 feeding 8 independent FMA chains. Register-prefetch (16 regs)
//   overlaps next subtile's LDG with compute. Occ 62% vs 46% at equal regs.

#define N_BATCH 16384
#define ROWS    32
#define RPT     8
#define NT      (ROWS / RPT)
#define TPB     640
#define PREP_T  1024
#define MAX_OUT 2048
#define P_SMEM  512
#define NSORT   512

__device__ uint4 g_paths[P_SMEM];     // binned + canonically ordered {r1,r2,cg,deg}
__device__ uint2 g_colinfo[MAX_OUT];  // {start | ns<<16, eff}

__device__ __forceinline__ int block_incl_scan(int v, int tid, int bd) {
    __shared__ int ws[32];
    int lane = tid & 31, wid = tid >> 5;
    __syncthreads();
    #pragma unroll
    for (int d = 1; d < 32; d <<= 1) {
        int t = __shfl_up_sync(0xffffffffu, v, d);
        if (lane >= d) v += t;
    }
    if (lane == 31) ws[wid] = v;
    __syncthreads();
    if (wid == 0) {
        int w = (lane < (bd >> 5)) ? ws[lane] : 0;
        #pragma unroll
        for (int d = 1; d < 32; d <<= 1) {
            int t = __shfl_up_sync(0xffffffffu, w, d);
            if (lane >= d) w += t;
        }
        ws[lane] = w;
    }
    __syncthreads();
    return v + (wid > 0 ? ws[wid - 1] : 0);
}

__global__ void prep_kernel(const void* r1v, const void* r2v, const void* rov,
                            const float* __restrict__ cg, int M, int out_dim) {
    __shared__ int   posu[NSORT];
    __shared__ int   sp[NSORT + 1];
    __shared__ uint4 praw[NSORT];
    __shared__ int   pro[NSORT];
    __shared__ uint4 pbin[P_SMEM];
    __shared__ int   cnt[MAX_OUT], stt[MAX_OUT];
    __shared__ int   s_is64, s_np;
    int tid = threadIdx.x, bd = blockDim.x;

    if (tid < 32) {
        const unsigned* w = (const unsigned*)r1v;
        int nw = M < 512 ? M : 512;
        int bad = 0;
        for (int i = 1 + 2 * tid; i < nw; i += 64) bad |= (w[i] != 0u);
        unsigned any = __ballot_sync(0xffffffffu, bad != 0);
        if (tid == 0) { s_is64 = (any == 0u); s_np = 0; }
    }
    __syncthreads();
    int sh = s_is64 ? 1 : 0;
    const int*      A1  = (const int*)r1v;
    const int*      A2  = (const int*)r2v;
    const int*      AO  = (const int*)rov;
    const unsigned* cgu = (const unsigned*)cg;
    #define IDX1(m) A1[(m) << sh]
    #define IDX2(m) A2[(m) << sh]
    #define IDXO(m) AO[(m) << sh]
    #define ISSTART(m) ((m) == 0 || \
        !(IDX1((m) - 1) + 1 == IDX1(m) && IDX2((m) - 1) + 1 == IDX2(m) && \
          IDXO((m) - 1) + 1 == IDXO(m) && cgu[(m) - 1] == cgu[m]))

    for (int m = tid; m < M; m += bd) {
        if (ISSTART(m)) {
            int k = atomicAdd(&s_np, 1);
            if (k < NSORT) posu[k] = m;
        }
    }
    __syncthreads();
    int P = s_np;
    if (P > NSORT) P = NSORT;
    for (int p = tid; p < P; p += bd) {
        int mypos = posu[p];
        int rank = 0;
        for (int q = 0; q < P; q++) rank += (posu[q] < mypos);
        sp[rank] = mypos;
    }
    if (tid == 0) sp[P] = M;
    __syncthreads();

    for (int p = tid; p < P; p += bd) {
        int s = sp[p];
        praw[p] = make_uint4((unsigned)IDX1(s), (unsigned)IDX2(s),
                             cgu[s], (unsigned)(sp[p + 1] - s));
        pro[p] = IDXO(s);
    }
    for (int i = tid; i < out_dim; i += bd) cnt[i] = 0;
    for (int i = tid; i < P_SMEM; i += bd) pbin[i] = make_uint4(0u, 0u, 0u, 0u);
    __syncthreads();

    for (int p = tid; p < P; p += bd) atomicAdd(&cnt[pro[p]], 1);
    __syncthreads();
    {
        int CH = (out_dim + bd - 1) / bd;
        int cb = tid * CH;
        int local = 0;
        for (int i = 0; i < CH; i++) { int idx = cb + i; if (idx < out_dim) local += cnt[idx]; }
        int incl = block_incl_scan(local, tid, bd);
        int run = incl - local;
        for (int i = 0; i < CH; i++) {
            int idx = cb + i;
            if (idx < out_dim) { stt[idx] = run; run += cnt[idx]; }
        }
    }
    __syncthreads();
    for (int p = tid; p < P; p += bd) {
        int b = pro[p];
        uint4 me = praw[p];
        int rank = 0;
        for (int q = 0; q < P; q++) {
            if (pro[q] == b) {
                uint4 o = praw[q];
                bool oFirst = (o.w > me.w) ||
                              (o.w == me.w && (o.x < me.x ||
                               (o.x == me.x && o.y < me.y)));
                rank += oFirst;
            }
        }
        pbin[stt[b] + rank] = me;
    }
    __syncthreads();

    for (int c = tid; c < out_dim; c += bd) {
        int b = c;
        while (b >= 0 && cnt[b] == 0) b--;
        uint2 info = make_uint2(0u, 0u);
        if (b >= 0) {
            int c0 = cnt[b], s0 = stt[b], ns = c - b, eff = 0;
            while (eff < c0 && (int)pbin[s0 + eff].w > ns) eff++;
            if (eff > 0)
                info = make_uint2((unsigned)s0 | ((unsigned)ns << 16), (unsigned)eff);
        }
        g_colinfo[c] = info;
    }
    for (int i = tid; i < P_SMEM; i += bd) g_paths[i] = pbin[i];
    #undef ISSTART
    #undef IDX1
    #undef IDX2
    #undef IDXO
}

// ===== couple: 8-row subtiles, 1 col/thread, TPB=640 =====
__global__ void __launch_bounds__(TPB, 2)
couple_kernel(const float* __restrict__ x1, const float* __restrict__ x2,
              float* __restrict__ out, int rep_dim, int out_dim) {
    extern __shared__ char smraw[];
    // x1s: [0,rep_dim) rows 0-3 interleaved; [rep_dim,2*rep_dim) rows 4-7
    float4* x1s = (float4*)smraw;
    float4* x2s = x1s + 2 * (size_t)rep_dim;
    uint2*  ci  = (uint2*)(x2s + 2 * (size_t)rep_dim);  // out_dim
    uint4*  pts = (uint4*)(ci + ((out_dim + 1) & ~1));  // P_SMEM paths

    int tid = threadIdx.x;
    for (int i = tid; i < P_SMEM; i += TPB) pts[i] = g_paths[i];
    for (int i = tid; i < out_dim; i += TPB) ci[i] = g_colinfo[i];

    int row0 = blockIdx.x * ROWS;
    int nstage = 2 * rep_dim;                 // float4 elements per array per subtile

    // stage subtile 0 directly
    {
        const float* a0 = x1 + (size_t)row0 * rep_dim;
        const float* b0 = x2 + (size_t)row0 * rep_dim;
        for (int i = tid; i < nstage; i += TPB) {
            int half = i / rep_dim;           // 0: rows 0-3, 1: rows 4-7
            int idx  = i - half * rep_dim;
            const float* a = a0 + (size_t)(4 * half) * rep_dim + idx;
            const float* b = b0 + (size_t)(4 * half) * rep_dim + idx;
            x1s[i] = make_float4(a[0], a[rep_dim], a[2 * rep_dim], a[3 * rep_dim]);
            x2s[i] = make_float4(b[0], b[rep_dim], b[2 * rep_dim], b[3 * rep_dim]);
        }
    }
    __syncthreads();

    // hoisted column info: thread reads exactly the ci entry it wrote (i = tid)
    int o0 = tid;
    uint2 c0 = (o0 < out_dim) ? ci[o0] : make_uint2(0u, 0u);
    int s0 = (int)(c0.x & 0xffffu), ne0 = (int)c0.y; unsigned ns0 = c0.x >> 16;

    for (int t = 0; t < NT; t++) {
        int r = row0 + t * RPT;

        // prefetch next subtile into registers (LDG in flight during compute)
        float4 pa[2], pb[2];
        if (t + 1 < NT) {
            const float* a0 = x1 + (size_t)(r + RPT) * rep_dim;
            const float* b0 = x2 + (size_t)(r + RPT) * rep_dim;
            #pragma unroll
            for (int k = 0; k < 2; k++) {
                int i = tid + k * TPB;
                if (i < nstage) {
                    int half = i / rep_dim;
                    int idx  = i - half * rep_dim;
                    const float* a = a0 + (size_t)(4 * half) * rep_dim + idx;
                    const float* b = b0 + (size_t)(4 * half) * rep_dim + idx;
                    pa[k] = make_float4(a[0], a[rep_dim], a[2 * rep_dim], a[3 * rep_dim]);
                    pb[k] = make_float4(b[0], b[rep_dim], b[2 * rep_dim], b[3 * rep_dim]);
                }
            }
        }

        // compute: 1 column, 8 rows (8 independent FMA chains)
        if (o0 < out_dim) {
            float a0c = 0.f, a1c = 0.f, a2c = 0.f, a3c = 0.f;
            float a4c = 0.f, a5c = 0.f, a6c = 0.f, a7c = 0.f;
            #pragma unroll 2
            for (int j = 0; j < ne0; j++) {
                uint4 p = pts[s0 + j];               // warp-uniform broadcast
                float cgv = __uint_as_float(p.z);
                float4 Al = x1s[p.x + ns0];          // rows 0-3, conflict-free
                float4 Bl = x2s[p.y + ns0];
                float4 Ah = x1s[rep_dim + p.x + ns0];  // rows 4-7
                float4 Bh = x2s[rep_dim + p.y + ns0];
                a0c = fmaf(Al.x * Bl.x, cgv, a0c);
                a1c = fmaf(Al.y * Bl.y, cgv, a1c);
                a2c = fmaf(Al.z * Bl.z, cgv, a2c);
                a3c = fmaf(Al.w * Bl.w, cgv, a3c);
                a4c = fmaf(Ah.x * Bh.x, cgv, a4c);
                a5c = fmaf(Ah.y * Bh.y, cgv, a5c);
                a6c = fmaf(Ah.z * Bh.z, cgv, a6c);
                a7c = fmaf(Ah.w * Bh.w, cgv, a7c);
            }
            float* ob = out + (size_t)r * out_dim + o0;
            ob[0]                   = a0c;
            ob[(size_t)out_dim]     = a1c;
            ob[(size_t)out_dim * 2] = a2c;
            ob[(size_t)out_dim * 3] = a3c;
            ob[(size_t)out_dim * 4] = a4c;
            ob[(size_t)out_dim * 5] = a5c;
            ob[(size_t)out_dim * 6] = a6c;
            ob[(size_t)out_dim * 7] = a7c;
        }
        // generic fallback for out_dim > TPB (not taken for this shape)
        for (int obase = TPB; obase < out_dim; obase += TPB) {
            int o = obase + tid;
            if (o < out_dim) {
                uint2 c = ci[o];
                int s = (int)(c.x & 0xffffu), ne = (int)c.y;
                unsigned ns = c.x >> 16;
                float acc[8];
                #pragma unroll
                for (int k = 0; k < 8; k++) acc[k] = 0.f;
                for (int j = 0; j < ne; j++) {
                    uint4 p = pts[s + j];
                    float cgv = __uint_as_float(p.z);
                    float4 Al = x1s[p.x + ns];
                    float4 Bl = x2s[p.y + ns];
                    float4 Ah = x1s[rep_dim + p.x + ns];
                    float4 Bh = x2s[rep_dim + p.y + ns];
                    acc[0] = fmaf(Al.x * Bl.x, cgv, acc[0]);
                    acc[1] = fmaf(Al.y * Bl.y, cgv, acc[1]);
                    acc[2] = fmaf(Al.z * Bl.z, cgv, acc[2]);
                    acc[3] = fmaf(Al.w * Bl.w, cgv, acc[3]);
                    acc[4] = fmaf(Ah.x * Bh.x, cgv, acc[4]);
                    acc[5] = fmaf(Ah.y * Bh.y, cgv, acc[5]);
                    acc[6] = fmaf(Ah.z * Bh.z, cgv, acc[6]);
                    acc[7] = fmaf(Ah.w * Bh.w, cgv, acc[7]);
                }
                float* ob = out + (size_t)r * out_dim + o;
                #pragma unroll
                for (int k = 0; k < 8; k++) ob[(size_t)out_dim * k] = acc[k];
            }
        }
        __syncthreads();   // everyone done reading the buffer

        if (t + 1 < NT) {
            #pragma unroll
            for (int k = 0; k < 2; k++) {
                int i = tid + k * TPB;
                if (i < nstage) { x1s[i] = pa[k]; x2s[i] = pb[k]; }
            }
            __syncthreads();   // buffer ready for next subtile
        }
    }
}

extern "C" void kernel_launch(void* const* d_in, const int* in_sizes, int n_in,
                              void* d_out, int out_size) {
    const float* x1 = (const float*)d_in[0];
    const float* x2 = (const float*)d_in[1];
    const float* cg = (const float*)d_in[2];
    const void*  r1 = d_in[3];
    const void*  r2 = d_in[4];
    const void*  ro = d_in[5];
    int M = in_sizes[2];
    int rep_dim = in_sizes[0] / N_BATCH;
    int out_dim = out_size / N_BATCH;

    prep_kernel<<<1, PREP_T>>>(r1, r2, ro, cg, M, out_dim);

    size_t smem = (size_t)rep_dim * 64 + (size_t)((out_dim + 1) & ~1) * 8
                + (size_t)P_SMEM * 16;
    cudaFuncSetAttribute(couple_kernel,
                         cudaFuncAttributeMaxDynamicSharedMemorySize, 200 * 1024);
    couple_kernel<<<N_BATCH / ROWS, TPB, smem>>>(x1, x2, (float*)d_out,
                                                 rep_dim, out_dim);
}